// round 6
// baseline (speedup 1.0000x reference)
#include <cuda_runtime.h>
#include <cuda_fp16.h>
#include <cstdint>
#include <mma.h>

using namespace nvcuda;

#define T_      8
#define H_      64
#define W_      64
#define C_      256
#define HEADS_  8
#define WS_     7
#define NPIX    (T_ * H_ * W_)          // 32768
#define M_      NPIX
#define N_      512
#define K_      256
#define NS_     (3 * WS_ * WS_)         // 147
#define SCALE_  0.17677669529663687f    // 32^-0.5

// scratch: q fp16 pre-scaled [pix][256], k fp16 [pix][256]
__device__ __align__(16) __half g_qh[(size_t)NPIX * 256];
__device__ __align__(16) __half g_kh[(size_t)NPIX * 256];

// ---------------------------------------------------------------------------
// GEMM: qk[m,n] = sum_k x[m,k] * W_qk[n,k]   tf32 WMMA, 128x64 tile, fp16 out
// ---------------------------------------------------------------------------
#define GBM 128
#define GBN 64
#define GLD 40

__global__ void __launch_bounds__(256) gemm_qk_kernel(
    const float* __restrict__ x, const float* __restrict__ wqk)
{
    __shared__ __align__(16) float S[9216];
    float* As = S;           // 128 x 40
    float* Bs = S + 5120;    // 64 x 40

    const int m0   = blockIdx.x * GBM;
    const int n0   = blockIdx.y * GBN;
    const int tid  = threadIdx.x;
    const int wid  = tid >> 5;
    const int lane = tid & 31;
    const int wm   = wid & 3;    // 4 M-groups of 32 rows
    const int wn   = wid >> 2;   // 2 N-groups of 32 cols

    wmma::fragment<wmma::accumulator, 16, 16, 8, float> acc[2][2];
    #pragma unroll
    for (int i = 0; i < 2; i++)
        #pragma unroll
        for (int j = 0; j < 2; j++)
            wmma::fill_fragment(acc[i][j], 0.0f);

    const int lr = tid >> 3;        // 0..31
    const int lc = (tid & 7) * 4;   // 0..28

    for (int kt = 0; kt < K_; kt += 32) {
        float4 a[4], b[2];
        #pragma unroll
        for (int i = 0; i < 4; i++)
            a[i] = *(const float4*)(x + (size_t)(m0 + lr + i * 32) * K_ + kt + lc);
        #pragma unroll
        for (int i = 0; i < 2; i++)
            b[i] = *(const float4*)(wqk + (size_t)(n0 + lr + i * 32) * K_ + kt + lc);
        #pragma unroll
        for (int i = 0; i < 4; i++) {
            a[i].x = wmma::__float_to_tf32(a[i].x); a[i].y = wmma::__float_to_tf32(a[i].y);
            a[i].z = wmma::__float_to_tf32(a[i].z); a[i].w = wmma::__float_to_tf32(a[i].w);
        }
        #pragma unroll
        for (int i = 0; i < 2; i++) {
            b[i].x = wmma::__float_to_tf32(b[i].x); b[i].y = wmma::__float_to_tf32(b[i].y);
            b[i].z = wmma::__float_to_tf32(b[i].z); b[i].w = wmma::__float_to_tf32(b[i].w);
        }
        __syncthreads();
        #pragma unroll
        for (int i = 0; i < 4; i++)
            *(float4*)(As + (lr + i * 32) * GLD + lc) = a[i];
        #pragma unroll
        for (int i = 0; i < 2; i++)
            *(float4*)(Bs + (lr + i * 32) * GLD + lc) = b[i];
        __syncthreads();

        #pragma unroll
        for (int kk = 0; kk < 32; kk += 8) {
            wmma::fragment<wmma::matrix_a, 16, 16, 8, wmma::precision::tf32, wmma::row_major> af0, af1;
            wmma::fragment<wmma::matrix_b, 16, 16, 8, wmma::precision::tf32, wmma::col_major> bf0, bf1;
            wmma::load_matrix_sync(af0, As + (wm * 32)      * GLD + kk, GLD);
            wmma::load_matrix_sync(af1, As + (wm * 32 + 16) * GLD + kk, GLD);
            wmma::load_matrix_sync(bf0, Bs + (wn * 32)      * GLD + kk, GLD);
            wmma::load_matrix_sync(bf1, Bs + (wn * 32 + 16) * GLD + kk, GLD);
            wmma::mma_sync(acc[0][0], af0, bf0, acc[0][0]);
            wmma::mma_sync(acc[0][1], af0, bf1, acc[0][1]);
            wmma::mma_sync(acc[1][0], af1, bf0, acc[1][0]);
            wmma::mma_sync(acc[1][1], af1, bf1, acc[1][1]);
        }
    }

    // epilogue: restage via smem, convert to fp16 (q pre-scaled by SCALE_)
    __syncthreads();
    float* wbuf = S + wid * 1152;   // 32 rows x pitch 36
    wmma::store_matrix_sync(wbuf,                acc[0][0], 36, wmma::mem_row_major);
    wmma::store_matrix_sync(wbuf + 16,           acc[0][1], 36, wmma::mem_row_major);
    wmma::store_matrix_sync(wbuf + 16 * 36,      acc[1][0], 36, wmma::mem_row_major);
    wmma::store_matrix_sync(wbuf + 16 * 36 + 16, acc[1][1], 36, wmma::mem_row_major);
    __syncwarp();

    const float sc = (n0 < 256) ? SCALE_ : 1.0f;
    const float* src = wbuf + lane * 36;
    uint4 o[4];
    #pragma unroll
    for (int i = 0; i < 4; i++) {
        float4 u = *(const float4*)(src + i * 8);
        float4 v = *(const float4*)(src + i * 8 + 4);
        __half2 p0 = __floats2half2_rn(u.x * sc, u.y * sc);
        __half2 p1 = __floats2half2_rn(u.z * sc, u.w * sc);
        __half2 p2 = __floats2half2_rn(v.x * sc, v.y * sc);
        __half2 p3 = __floats2half2_rn(v.z * sc, v.w * sc);
        o[i].x = *(unsigned*)&p0; o[i].y = *(unsigned*)&p1;
        o[i].z = *(unsigned*)&p2; o[i].w = *(unsigned*)&p3;
    }
    const int gr = m0 + wm * 32 + lane;
    const int gc = n0 + wn * 32;
    __half* dst = (n0 < 256) ? (g_qh + (size_t)gr * 256 + gc)
                             : (g_kh + (size_t)gr * 256 + (gc - 256));
    *(uint4*)(dst)      = o[0];
    *(uint4*)(dst + 8)  = o[1];
    *(uint4*)(dst + 16) = o[2];
    *(uint4*)(dst + 24) = o[3];
}

// ---------------------------------------------------------------------------
// Attention: one block per pixel; gathered K staged to smem via cp.async,
// scores via mma.sync m16n8k16 (A = K rows, B = block-diag Q, built in regs)
// ---------------------------------------------------------------------------
#define KPITCH 264                      // halfs per staged row (256 + 8 pad)
#define SM_BYTES 92160

__device__ __forceinline__ int reflect_idx(int idx, int L)
{
    const int period = 2 * (L - 1);
    int m = idx % period;
    if (m < 0) m += period;
    return (m > L - 1) ? (period - m) : m;
}

__global__ void __launch_bounds__(256) attn_kernel(
    const float* __restrict__ flows, float* __restrict__ out)
{
    extern __shared__ __align__(16) char sm[];
    __half*   Kst    = (__half*)sm;                    // 160 x 264 halfs = 84480 B
    uint32_t* qh2    = (uint32_t*)(sm + 84480);        // 128 u32 (256 halfs)
    float*    attn_s = (float*)(sm + 84992);           // 1176 f32
    float*    fl_s   = (float*)(sm + 89696);           // 441 f32
    int*      off_s  = (int*)(sm + 91472);             // 147 used
    int*      s_fl   = (int*)(sm + 92112);             // 4

    const int pix = blockIdx.x;
    const int t   = pix >> 12;
    const int hw  = pix & 4095;
    const int h   = hw >> 6;
    const int w   = hw & 63;

    const int tid  = threadIdx.x;
    const int warp = tid >> 5;
    const int lane = tid & 31;

    if (tid < 4) {
        const int p_ = tid >> 1, c_ = tid & 1;
        s_fl[tid] = (int)rintf(flows[(size_t)((t * 2 + p_) * 2 + c_) * 4096 + hw]);
    }
    if (tid < 128)
        qh2[tid] = ((const uint32_t*)(g_qh + (size_t)pix * 256))[tid];
    __syncthreads();

    if (tid < NS_) {
        const int slot = (tid >= 49) + (tid >= 98);
        const int r    = tid - slot * 49;
        const int a    = r / 7;
        const int b    = r - a * 7;
        int di = 0, dj = 0, tp = t;
        if (slot == 1) { tp = (t + 1 < T_) ? t + 1 : t - 2; di = s_fl[0]; dj = s_fl[1]; }
        if (slot == 2) { tp = (t - 1 >= 0) ? t - 1 : t + 2; di = s_fl[2]; dj = s_fl[3]; }
        const int li = reflect_idx(h + di + a - 3, H_);
        const int lj = reflect_idx(w + dj + b - 3, W_);
        off_s[tid] = (tp << 12) + li * 64 + lj;
        fl_s[tid * 3 + 0] = (float)(tp - t);
        fl_s[tid * 3 + 1] = (float)(li - h);
        fl_s[tid * 3 + 2] = (float)(lj - w);
    }
    __syncthreads();

    // ---- stage gathered K rows into smem (cp.async, 16B per lane per row) ----
    for (int r = warp; r < NS_; r += 8) {
        const __half* src = g_kh + (((size_t)off_s[r]) << 8) + lane * 8;
        uint32_t dst = (uint32_t)__cvta_generic_to_shared(Kst + r * KPITCH + lane * 8);
        asm volatile("cp.async.cg.shared.global [%0], [%1], 16;\n"
                     :: "r"(dst), "l"(src) : "memory");
    }
    asm volatile("cp.async.commit_group;\n" ::: "memory");

    // ---- build block-diagonal B fragments in registers (no smem, no ldsm) ----
    const int gid = lane >> 2;       // 0..7  (= key-row / n-column role)
    const int tig = lane & 3;        // 0..3
    uint32_t bfr[16][2];
    #pragma unroll
    for (int kt = 0; kt < 16; kt++) {
        const bool act = (gid == (kt >> 1));
        bfr[kt][0] = act ? qh2[kt * 8 + tig]     : 0u;
        bfr[kt][1] = act ? qh2[kt * 8 + 4 + tig] : 0u;
    }

    // ---- flows_k stores overlapped with cp.async completion ----
    const size_t FBASE = (size_t)HEADS_ * T_ * 4096 * NS_;  // 38,535,168
    #pragma unroll
    for (int head = 0; head < HEADS_; head++) {
        for (int idx = tid; idx < NS_ * 3; idx += 256)
            out[FBASE + (size_t)((head * T_ + t) * 4096 + hw) * (NS_ * 3) + idx] = fl_s[idx];
    }

    asm volatile("cp.async.wait_group 0;\n" ::: "memory");
    __syncthreads();

    // ---- tensor-core score computation: 10 m16 tiles over 8 warps ----
    #pragma unroll
    for (int pass = 0; pass < 2; pass++) {
        const int mt = warp + pass * 8;
        if (mt <= 9) {
            float c0 = 0.f, c1 = 0.f, c2 = 0.f, c3 = 0.f;
            uint32_t abase = (uint32_t)__cvta_generic_to_shared(
                Kst + (mt * 16 + (lane & 15)) * KPITCH + (lane >> 4) * 8);
            #pragma unroll
            for (int kt = 0; kt < 16; kt++) {
                uint32_t a0, a1, a2, a3;
                asm volatile("ldmatrix.sync.aligned.m8n8.x4.shared.b16 {%0,%1,%2,%3}, [%4];\n"
                             : "=r"(a0), "=r"(a1), "=r"(a2), "=r"(a3)
                             : "r"(abase + kt * 32));
                asm volatile("mma.sync.aligned.m16n8k16.row.col.f32.f16.f16.f32 "
                             "{%0,%1,%2,%3}, {%4,%5,%6,%7}, {%8,%9}, {%0,%1,%2,%3};\n"
                             : "+f"(c0), "+f"(c1), "+f"(c2), "+f"(c3)
                             : "r"(a0), "r"(a1), "r"(a2), "r"(a3),
                               "r"(bfr[kt][0]), "r"(bfr[kt][1]));
            }
            const int s0 = mt * 16 + gid;
            const int h0 = tig * 2;
            if (s0 < NS_) {
                attn_s[h0 * NS_ + s0]       = c0;
                attn_s[(h0 + 1) * NS_ + s0] = c1;
            }
            if (s0 + 8 < NS_) {
                attn_s[h0 * NS_ + s0 + 8]       = c2;
                attn_s[(h0 + 1) * NS_ + s0 + 8] = c3;
            }
        }
    }
    __syncthreads();

    // ---- attn stores: (1, HEADS, T, H, W, 147) ----
    #pragma unroll
    for (int head = 0; head < HEADS_; head++) {
        if (tid < NS_)
            out[(size_t)((head * T_ + t) * 4096 + hw) * NS_ + tid] = attn_s[head * NS_ + tid];
    }
}

// ---------------------------------------------------------------------------
extern "C" void kernel_launch(void* const* d_in, const int* in_sizes, int n_in,
                              void* d_out, int out_size)
{
    const float* x     = (const float*)d_in[0];   // (8,64,64,256)
    const float* flows = (const float*)d_in[1];   // (1,8,2,2,64,64)
    const float* wqk   = (const float*)d_in[2];   // (512,256)
    float* out = (float*)d_out;

    cudaFuncSetAttribute(attn_kernel,
                         cudaFuncAttributeMaxDynamicSharedMemorySize, SM_BYTES);

    dim3 gg(M_ / GBM, N_ / GBN);
    gemm_qk_kernel<<<gg, 256>>>(x, wqk);
    attn_kernel<<<NPIX, 256, SM_BYTES>>>(flows, out);
}

// round 7
// speedup vs baseline: 1.9057x; 1.9057x over previous
#include <cuda_runtime.h>
#include <cuda_fp16.h>
#include <cstdint>
#include <mma.h>

using namespace nvcuda;

#define T_      8
#define H_      64
#define W_      64
#define C_      256
#define HEADS_  8
#define WS_     7
#define NPIX    (T_ * H_ * W_)          // 32768
#define M_      NPIX
#define N_      512
#define K_      256
#define NS_     (3 * WS_ * WS_)         // 147
#define SCALE_  0.17677669529663687f    // 32^-0.5

// fp16 copies of inputs
__device__ __align__(16) __half g_xh[(size_t)NPIX * 256];
__device__ __align__(16) __half g_wh[(size_t)512 * 256];
// projected q (pre-scaled) / k, fp16
__device__ __align__(16) __half g_qh[(size_t)NPIX * 256];
__device__ __align__(16) __half g_kh[(size_t)NPIX * 256];

// ---------------------------------------------------------------------------
// convert x, W_qk to fp16
// ---------------------------------------------------------------------------
#define XN_ (NPIX * 256)          // 8388608
#define WN_ (512 * 256)           // 131072

__global__ void __launch_bounds__(256) cvt_kernel(
    const float* __restrict__ x, const float* __restrict__ wqk)
{
    const int idx = blockIdx.x * blockDim.x + threadIdx.x;   // 8-float chunk id
    const long base = (long)idx * 8;
    const float* src;
    __half* dst;
    if (base < XN_) { src = x + base;           dst = g_xh + base; }
    else            { src = wqk + (base - XN_); dst = g_wh + (base - XN_); }
    const float4 u = *(const float4*)(src);
    const float4 v = *(const float4*)(src + 4);
    __half2 p0 = __floats2half2_rn(u.x, u.y);
    __half2 p1 = __floats2half2_rn(u.z, u.w);
    __half2 p2 = __floats2half2_rn(v.x, v.y);
    __half2 p3 = __floats2half2_rn(v.z, v.w);
    uint4 o;
    o.x = *(unsigned*)&p0; o.y = *(unsigned*)&p1;
    o.z = *(unsigned*)&p2; o.w = *(unsigned*)&p3;
    *(uint4*)dst = o;
}

// ---------------------------------------------------------------------------
// GEMM: qk[m,n] = sum_k x[m,k] * W_qk[n,k]   fp16 WMMA, 128x128 tile
// ---------------------------------------------------------------------------
#define GBM 128
#define GBN 128
#define GLD 40          // halfs pitch

__global__ void __launch_bounds__(256) gemm_qk_kernel()
{
    __shared__ __align__(16) char SB[40960];
    __half* As = (__half*)SB;            // 128 x 40
    __half* Bs = As + 5120;              // 128 x 40

    const int m0   = blockIdx.x * GBM;
    const int n0   = blockIdx.y * GBN;
    const int tid  = threadIdx.x;
    const int wid  = tid >> 5;
    const int lane = tid & 31;
    const int wm   = wid & 3;    // 4 M-groups of 32 rows
    const int wn   = wid >> 2;   // 2 N-groups of 64 cols

    wmma::fragment<wmma::accumulator, 16, 16, 16, float> acc[2][4];
    #pragma unroll
    for (int i = 0; i < 2; i++)
        #pragma unroll
        for (int j = 0; j < 4; j++)
            wmma::fill_fragment(acc[i][j], 0.0f);

    const int lr = tid >> 1;            // 0..127
    const int lc = (tid & 1) * 16;      // 0 or 16

    for (int kt = 0; kt < K_; kt += 32) {
        const uint4 a0 = *(const uint4*)(g_xh + (size_t)(m0 + lr) * 256 + kt + lc);
        const uint4 a1 = *(const uint4*)(g_xh + (size_t)(m0 + lr) * 256 + kt + lc + 8);
        const uint4 b0 = *(const uint4*)(g_wh + (size_t)(n0 + lr) * 256 + kt + lc);
        const uint4 b1 = *(const uint4*)(g_wh + (size_t)(n0 + lr) * 256 + kt + lc + 8);
        __syncthreads();
        *(uint4*)(As + lr * GLD + lc)     = a0;
        *(uint4*)(As + lr * GLD + lc + 8) = a1;
        *(uint4*)(Bs + lr * GLD + lc)     = b0;
        *(uint4*)(Bs + lr * GLD + lc + 8) = b1;
        __syncthreads();

        #pragma unroll
        for (int kk = 0; kk < 32; kk += 16) {
            wmma::fragment<wmma::matrix_a, 16, 16, 16, __half, wmma::row_major> af0, af1;
            wmma::load_matrix_sync(af0, As + (wm * 32)      * GLD + kk, GLD);
            wmma::load_matrix_sync(af1, As + (wm * 32 + 16) * GLD + kk, GLD);
            #pragma unroll
            for (int j = 0; j < 4; j++) {
                wmma::fragment<wmma::matrix_b, 16, 16, 16, __half, wmma::col_major> bf;
                wmma::load_matrix_sync(bf, Bs + (wn * 64 + j * 16) * GLD + kk, GLD);
                wmma::mma_sync(acc[0][j], af0, bf, acc[0][j]);
                wmma::mma_sync(acc[1][j], af1, bf, acc[1][j]);
            }
        }
    }

    // epilogue: restage 16 rows at a time, convert to fp16 (q pre-scaled)
    __syncthreads();
    float* wbuf = (float*)SB + wid * 1088;   // 16 rows x pitch 68
    const float sc = (n0 < 256) ? SCALE_ : 1.0f;
    const int row  = lane >> 1;
    const int colh = (lane & 1) * 32;

    #pragma unroll
    for (int i = 0; i < 2; i++) {
        #pragma unroll
        for (int j = 0; j < 4; j++)
            wmma::store_matrix_sync(wbuf + j * 16, acc[i][j], 68, wmma::mem_row_major);
        __syncwarp();

        const float* src = wbuf + row * 68 + colh;
        uint4 o[2];
        #pragma unroll
        for (int g = 0; g < 2; g++) {
            float4 u0 = *(const float4*)(src + g * 16);
            float4 u1 = *(const float4*)(src + g * 16 + 4);
            float4 u2 = *(const float4*)(src + g * 16 + 8);
            float4 u3 = *(const float4*)(src + g * 16 + 12);
            __half2 p0 = __floats2half2_rn(u0.x * sc, u0.y * sc);
            __half2 p1 = __floats2half2_rn(u0.z * sc, u0.w * sc);
            __half2 p2 = __floats2half2_rn(u1.x * sc, u1.y * sc);
            __half2 p3 = __floats2half2_rn(u1.z * sc, u1.w * sc);
            __half2 p4 = __floats2half2_rn(u2.x * sc, u2.y * sc);
            __half2 p5 = __floats2half2_rn(u2.z * sc, u2.w * sc);
            __half2 p6 = __floats2half2_rn(u3.x * sc, u3.y * sc);
            __half2 p7 = __floats2half2_rn(u3.z * sc, u3.w * sc);
            o[0].x = *(unsigned*)&p0; o[0].y = *(unsigned*)&p1;
            o[0].z = *(unsigned*)&p2; o[0].w = *(unsigned*)&p3;
            o[1].x = *(unsigned*)&p4; o[1].y = *(unsigned*)&p5;
            o[1].z = *(unsigned*)&p6; o[1].w = *(unsigned*)&p7;
            const int gr = m0 + wm * 32 + i * 16 + row;
            const int gc = n0 + wn * 64 + colh + g * 16;   // 16 halfs per uint4 pair? no: 16 floats -> 16 halfs = 2 uint4? (8 halfs each)
            __half* dst = (n0 < 256) ? (g_qh + (size_t)gr * 256 + gc)
                                     : (g_kh + (size_t)gr * 256 + (gc - 256));
            *(uint4*)(dst)     = o[0];
            *(uint4*)(dst + 8) = o[1];
        }
        __syncwarp();
    }
}

// ---------------------------------------------------------------------------
// Attention: one block per pixel, one warp per key, HFMA2 dot products
// ---------------------------------------------------------------------------
__device__ __forceinline__ int reflect_idx(int idx, int L)
{
    const int period = 2 * (L - 1);
    int m = idx % period;
    if (m < 0) m += period;
    return (m > L - 1) ? (period - m) : m;
}

__global__ void __launch_bounds__(256) attn_kernel(
    const float* __restrict__ flows, float* __restrict__ out)
{
    const int pix = blockIdx.x;
    const int t   = pix >> 12;
    const int hw  = pix & 4095;
    const int h   = hw >> 6;
    const int w   = hw & 63;

    __shared__ int   off_s[NS_];
    __shared__ float fl_s[NS_ * 3];
    __shared__ float attn_s[HEADS_ * NS_];
    __shared__ int   s_fl[4];

    const int tid  = threadIdx.x;
    const int warp = tid >> 5;
    const int lane = tid & 31;

    if (tid < 4) {
        const int p_ = tid >> 1, c_ = tid & 1;
        s_fl[tid] = (int)rintf(flows[(size_t)((t * 2 + p_) * 2 + c_) * 4096 + hw]);
    }

    // q fragment (pre-scaled fp16): lane covers channels 8*lane..8*lane+7
    const uint4 qv = *(const uint4*)(g_qh + (size_t)pix * 256 + lane * 8);
    const __half2 q0 = *(const __half2*)&qv.x;
    const __half2 q1 = *(const __half2*)&qv.y;
    const __half2 q2 = *(const __half2*)&qv.z;
    const __half2 q3 = *(const __half2*)&qv.w;

    __syncthreads();   // s_fl ready

    if (tid < NS_) {
        const int slot = (tid >= 49) + (tid >= 98);
        const int r    = tid - slot * 49;
        const int a    = r / 7;
        const int b    = r - a * 7;
        int di = 0, dj = 0, tp = t;
        if (slot == 1) { tp = (t + 1 < T_) ? t + 1 : t - 2; di = s_fl[0]; dj = s_fl[1]; }
        if (slot == 2) { tp = (t - 1 >= 0) ? t - 1 : t + 2; di = s_fl[2]; dj = s_fl[3]; }
        const int li = reflect_idx(h + di + a - 3, H_);
        const int lj = reflect_idx(w + dj + b - 3, W_);
        off_s[tid] = (tp << 12) + li * 64 + lj;
        fl_s[tid * 3 + 0] = (float)(tp - t);
        fl_s[tid * 3 + 1] = (float)(li - h);
        fl_s[tid * 3 + 2] = (float)(lj - w);
    }
    __syncthreads();

    const __half* kb = g_kh + lane * 8;   // per-lane base

    #pragma unroll 2
    for (int s = warp; s < NS_; s += 8) {
        const int off = off_s[s];                           // LDS broadcast
        const uint4 kv = *(const uint4*)(kb + ((size_t)off << 8));
        const __half2 k0 = *(const __half2*)&kv.x;
        const __half2 k1 = *(const __half2*)&kv.y;
        const __half2 k2 = *(const __half2*)&kv.z;
        const __half2 k3 = *(const __half2*)&kv.w;
        __half2 acc = __hmul2(k0, q0);
        acc = __hfma2(k1, q1, acc);
        acc = __hfma2(k2, q2, acc);
        acc = __hfma2(k3, q3, acc);
        float p = __half2float(__hadd(__low2half(acc), __high2half(acc)));
        p += __shfl_xor_sync(0xffffffffu, p, 1);
        p += __shfl_xor_sync(0xffffffffu, p, 2);
        if ((lane & 3) == 0)
            attn_s[(lane >> 2) * NS_ + s] = p;              // head = lane>>2
    }
    __syncthreads();

    // attn: (1, HEADS, T, H, W, 147)
    #pragma unroll
    for (int head = 0; head < HEADS_; head++) {
        if (tid < NS_)
            out[(size_t)((head * T_ + t) * 4096 + hw) * NS_ + tid] = attn_s[head * NS_ + tid];
    }

    // flows_k: (1, HEADS, T, H, W, 147, 3)
    const size_t FBASE = (size_t)HEADS_ * T_ * 4096 * NS_;  // 38,535,168
    #pragma unroll
    for (int head = 0; head < HEADS_; head++) {
        for (int idx = tid; idx < NS_ * 3; idx += 256)
            out[FBASE + (size_t)((head * T_ + t) * 4096 + hw) * (NS_ * 3) + idx] = fl_s[idx];
    }
}

// ---------------------------------------------------------------------------
extern "C" void kernel_launch(void* const* d_in, const int* in_sizes, int n_in,
                              void* d_out, int out_size)
{
    const float* x     = (const float*)d_in[0];   // (8,64,64,256)
    const float* flows = (const float*)d_in[1];   // (1,8,2,2,64,64)
    const float* wqk   = (const float*)d_in[2];   // (512,256)
    float* out = (float*)d_out;

    cvt_kernel<<<(XN_ + WN_) / 8 / 256, 256>>>(x, wqk);
    dim3 gg(M_ / GBM, N_ / GBN);
    gemm_qk_kernel<<<gg, 256>>>();
    attn_kernel<<<NPIX, 256>>>(flows, out);
}